// round 4
// baseline (speedup 1.0000x reference)
#include <cuda_runtime.h>

// ConvSpatialPropagationNet — the reference's propagation is a fixed point at
// d0 = blur_depth: the gates multiply depth at the SAME padded coordinate, so
// nws == gate_sum * d and the recurrence d <- (1-g)*raw + g*d, d0 = raw,
// never moves (verified in R1/R2: rel_err ~6e-8 = reference's own fp drift).
// Output = copy of blur_depth (13.7 MB).
//
// R4 (R3 retry after infra failure): route the copy through the copy engine.
// A D2D cudaMemcpyAsync on the capture stream records a single CE memcpy node
// in the CUDA graph — no CTA launch ramp, no occupancy/issue stalls; CE D2D
// runs near HBM peak. Harness rules explicitly allow async D2D memcpy.

extern "C" void kernel_launch(void* const* d_in, const int* in_sizes, int n_in,
                              void* d_out, int out_size) {
    // Input order per metadata: guidance, blur_depth, sparse_depth, sum_w
    const float* blur_depth = (const float*)d_in[1];
    float* out = (float*)d_out;
    const size_t bytes = (size_t)out_size * sizeof(float);

    cudaMemcpyAsync(out, blur_depth, bytes, cudaMemcpyDeviceToDevice, 0);
}